// round 11
// baseline (speedup 1.0000x reference)
#include <cuda_runtime.h>
#include <cuda_fp16.h>
#include <cuda_bf16.h>
#include <stdint.h>

// Problem constants
#define OUTF   11008
#define INF    4096
#define MTOT   512
#define NUM_GROUPS 1409024               // OUTF*INF/32

#define N_TILE 128
#define M_TILE 128
#define KCHUNK 64
#define KSPLIT 4
#define NCHUNK_JOB (INF / KCHUNK / KSPLIT)   // 16 chunks per job
#define NTHREADS 128                     // 4 warps, warp tile m64 x n64

#define PITCH 144                        // 128B data + 16B pad per row (conflict-free ldmatrix)
#define STAGE_BYTES (128 * PITCH)        // 18432 per tile (A or B)
// A: 3 stages, B: 2 stages
#define SMEM_BYTES (1024 + 5 * STAGE_BYTES)  // 93184 -> 2 CTAs/SM (186KB of 228KB)

// element counts for input identification (all distinct)
#define N_X   (MTOT * INF)               // 2,097,152 fp32
#define N_WQ  (NUM_GROUPS * 12)          // 16,908,288 int32
#define N_WN  NUM_GROUPS                 // 1,409,024 (dtype auto-detected)
#define N_B   OUTF                       // 11,008 fp32

// prep kernel block partition (512 threads each)
#define NB_WN  (NUM_GROUPS / 512)        // 2752
#define NB_X   (MTOT * INF / 2 / 512)    // 2048
#define NB_OUT (MTOT * OUTF / 4 / 512)   // 2752

__device__ __align__(16) __half g_xh[MTOT * INF];   // fp16-converted activations (4 MB)
__device__ __align__(16) __half g_wn[NUM_GROUPS];   // normalized norms (2.8 MB)

// ---------------- helpers ----------------
__device__ __forceinline__ uint32_t smem_u32(const void* p) {
    uint32_t a;
    asm("{ .reg .u64 t; cvta.to.shared.u64 t, %1; cvt.u32.u64 %0, t; }" : "=r"(a) : "l"(p));
    return a;
}

__device__ __forceinline__ void sts128(uint32_t addr, uint4 v) {
    asm volatile("st.shared.v4.b32 [%0], {%1,%2,%3,%4};"
                 :: "r"(addr), "r"(v.x), "r"(v.y), "r"(v.z), "r"(v.w) : "memory");
}

__device__ __forceinline__ void cpasync16(uint32_t dst, const void* src) {
    asm volatile("cp.async.cg.shared.global [%0], [%1], 16;" :: "r"(dst), "l"(src) : "memory");
}

__device__ __forceinline__ void ldm_x4(uint32_t* r, uint32_t addr) {
    asm volatile("ldmatrix.sync.aligned.m8n8.x4.shared.b16 {%0,%1,%2,%3}, [%4];"
                 : "=r"(r[0]), "=r"(r[1]), "=r"(r[2]), "=r"(r[3]) : "r"(addr));
}

__device__ __forceinline__ void mma16816(float* c, const uint32_t* a, const uint32_t b0, const uint32_t b1) {
    asm volatile(
        "mma.sync.aligned.m16n8k16.row.col.f32.f16.f16.f32 "
        "{%0,%1,%2,%3}, {%4,%5,%6,%7}, {%8,%9}, {%0,%1,%2,%3};"
        : "+f"(c[0]), "+f"(c[1]), "+f"(c[2]), "+f"(c[3])
        : "r"(a[0]), "r"(a[1]), "r"(a[2]), "r"(a[3]), "r"(b0), "r"(b1));
}

// Decode 8 3-bit codes from 3 bytes (each held in an int32), dequantize, pack to 4x half2.
__device__ __forceinline__ uint4 dec8(int b0, int b1, int b2, float a, float nb) {
    float w0 = fmaf((float)(b0 & 7), a, nb);
    float w1 = fmaf((float)((b0 >> 3) & 7), a, nb);
    float w2 = fmaf((float)(((b0 >> 6) & 3) | ((b1 & 1) << 2)), a, nb);
    float w3 = fmaf((float)((b1 >> 1) & 7), a, nb);
    float w4 = fmaf((float)((b1 >> 4) & 7), a, nb);
    float w5 = fmaf((float)(((b1 >> 7) & 1) | ((b2 & 3) << 1)), a, nb);
    float w6 = fmaf((float)((b2 >> 2) & 7), a, nb);
    float w7 = fmaf((float)((b2 >> 5) & 7), a, nb);
    uint4 u;
    asm("cvt.rn.f16x2.f32 %0, %1, %2;" : "=r"(u.x) : "f"(w1), "f"(w0));
    asm("cvt.rn.f16x2.f32 %0, %1, %2;" : "=r"(u.y) : "f"(w3), "f"(w2));
    asm("cvt.rn.f16x2.f32 %0, %1, %2;" : "=r"(u.z) : "f"(w5), "f"(w4));
    asm("cvt.rn.f16x2.f32 %0, %1, %2;" : "=r"(u.w) : "f"(w7), "f"(w6));
    return u;
}

// ---------------- fused prep: wn detect+convert, x convert, out init ----------------
// Norms lie in (0.01, 0.11); each wn-block re-votes locally (no serial detect launch).
__global__ void __launch_bounds__(512) prep_kernel(
    const void* __restrict__ wn, const float* __restrict__ x,
    const float* __restrict__ bias, float* __restrict__ out)
{
    int b = blockIdx.x;
    if (b < NB_WN) {
        __shared__ int votes[3];
        if (threadIdx.x < 3) votes[threadIdx.x] = 0;
        __syncthreads();
        {
            int j = threadIdx.x & 255;
            float a = ((const float*)wn)[j];
            float h = __half2float(((const __half*)wn)[j]);
            float c = __bfloat162float(((const __nv_bfloat16*)wn)[j]);
            if (a > 0.009f && a < 0.115f) atomicAdd(&votes[0], 1);
            if (h > 0.009f && h < 0.115f) atomicAdd(&votes[1], 1);
            if (c > 0.009f && c < 0.115f) atomicAdd(&votes[2], 1);
        }
        __syncthreads();
        int mode = 1, best = votes[1];
        if (votes[0] > best) { best = votes[0]; mode = 0; }
        if (votes[2] > best) { best = votes[2]; mode = 2; }
        int i = b * 512 + threadIdx.x;
        float v;
        if (mode == 0)      v = ((const float*)wn)[i];
        else if (mode == 1) v = __half2float(((const __half*)wn)[i]);
        else                v = __bfloat162float(((const __nv_bfloat16*)wn)[i]);
        g_wn[i] = __float2half_rn(v);
    } else if (b < NB_WN + NB_X) {
        int i = (b - NB_WN) * 512 + threadIdx.x;
        float2 v = ((const float2*)x)[i];
        ((__half2*)g_xh)[i] = __floats2half2_rn(v.x, v.y);
    } else {
        int i = (b - NB_WN - NB_X) * 512 + threadIdx.x;     // float4 index
        int n4 = (i % (OUTF / 4)) * 4;
        float4 bb = *(const float4*)(bias + n4);
        ((float4*)out)[i] = bb;
    }
}

// ---------------- fused dequant + GEMM, split-K, 4 warps @ m64n64 warp tile ----------------
__global__ void __launch_bounds__(NTHREADS, 2) l3b_gemm(
    const int* __restrict__ wq, float* __restrict__ out)
{
    extern __shared__ char smem[];
    const uint32_t sb = smem_u32(smem);
    const int tid = threadIdx.x;
    const int wid = tid >> 5, lid = tid & 31;
    const int wm = wid >> 1, wn_ = wid & 1;          // 2x2 warp grid, warp tile m64 x n64
    const int m0 = blockIdx.x * M_TILE;              // m fast-varying: L2 weight reuse
    const int n0 = blockIdx.y * N_TILE;
    const int c0 = blockIdx.z * NCHUNK_JOB;          // split-K chunk base

    const uint32_t As0 = sb + 1024;                  // 3 A stages
    const uint32_t Bb  = As0 + 3 * STAGE_BYTES;      // 2 B stages

    // dequant task: thread -> row tid (0..127); BOTH 32-groups of each 64-K chunk.
    // Groups g0 = (n0+tid)*128 + ci*2 and g0+1 are contiguous: 6 int4 + half2 norm.
    const long gbase = (long)(n0 + tid) * (INF / 32);
    const uint32_t brow = (uint32_t)(tid * PITCH);

    // ldmatrix lane addressing
    const uint32_t a_lrow = (uint32_t)(lid & 15);
    const uint32_t a_lkoff = (uint32_t)((lid >> 4) * 8);
    const uint32_t b_lrow = (uint32_t)(((lid >> 4) << 3) + (lid & 7));
    const uint32_t b_lkoff = (uint32_t)(((lid >> 3) & 1) * 8);

    float acc[4][8][4];
    #pragma unroll
    for (int mt = 0; mt < 4; mt++)
        #pragma unroll
        for (int nt = 0; nt < 8; nt++)
            #pragma unroll
            for (int e = 0; e < 4; e++) acc[mt][nt][e] = 0.0f;

    // ---- prologue: stage A(c0)->A0, A(c0+1)->A1, B(c0)->B0 ----
    {
        #pragma unroll
        for (int p = 0; p < 8; p++) {
            int idx = p * NTHREADS + tid;                 // 0..1023
            int row = idx >> 3, col = idx & 7;
            cpasync16(As0 + (uint32_t)(row * PITCH + col * 16),
                      g_xh + (size_t)(m0 + row) * INF + c0 * KCHUNK + col * 8);
        }
        asm volatile("cp.async.commit_group;" ::: "memory");
        #pragma unroll
        for (int p = 0; p < 8; p++) {
            int idx = p * NTHREADS + tid;
            int row = idx >> 3, col = idx & 7;
            cpasync16(As0 + STAGE_BYTES + (uint32_t)(row * PITCH + col * 16),
                      g_xh + (size_t)(m0 + row) * INF + (c0 + 1) * KCHUNK + col * 8);
        }
        asm volatile("cp.async.commit_group;" ::: "memory");

        const long g = gbase + c0 * 2;
        const int4* pk = (const int4*)wq + g * 3;
        int4 w0 = __ldg(pk),     w1 = __ldg(pk + 1), w2 = __ldg(pk + 2);
        int4 w3 = __ldg(pk + 3), w4 = __ldg(pk + 4), w5 = __ldg(pk + 5);
        __half2 nn = __ldg((const __half2*)(g_wn + g));
        float n0f = __half2float(__low2half(nn)), n1f = __half2float(__high2half(nn));
        float a0 = n0f * (2.0f / 7.0f), nb0 = -n0f;
        float a1 = n1f * (2.0f / 7.0f), nb1 = -n1f;
        sts128(Bb + brow +  0, dec8(w0.x, w0.y, w0.z, a0, nb0));
        sts128(Bb + brow + 16, dec8(w0.w, w1.x, w1.y, a0, nb0));
        sts128(Bb + brow + 32, dec8(w1.z, w1.w, w2.x, a0, nb0));
        sts128(Bb + brow + 48, dec8(w2.y, w2.z, w2.w, a0, nb0));
        sts128(Bb + brow + 64, dec8(w3.x, w3.y, w3.z, a1, nb1));
        sts128(Bb + brow + 80, dec8(w3.w, w4.x, w4.y, a1, nb1));
        sts128(Bb + brow + 96, dec8(w4.z, w4.w, w5.x, a1, nb1));
        sts128(Bb + brow + 112, dec8(w5.y, w5.z, w5.w, a1, nb1));
        asm volatile("cp.async.wait_group 1;" ::: "memory");   // A(c0) landed
        __syncthreads();
    }

    int rd3 = 0;                                     // A read stage (i % 3)

    #pragma unroll 1
    for (int i = 0; i < NCHUNK_JOB; i++) {
        const uint32_t As = As0 + (uint32_t)rd3 * STAGE_BYTES;
        const uint32_t Bs = Bb + (uint32_t)(i & 1) * STAGE_BYTES;

        // ---- prefetch B(i+1) packed words into registers ----
        int4 w0, w1, w2, w3, w4, w5;
        float a0 = 0.f, nb0 = 0.f, a1 = 0.f, nb1 = 0.f;
        const bool more = (i + 1 < NCHUNK_JOB);
        const bool more2 = (i + 2 < NCHUNK_JOB);
        if (more) {
            const long g = gbase + (c0 + i + 1) * 2;
            const int4* pk = (const int4*)wq + g * 3;
            w0 = __ldg(pk);     w1 = __ldg(pk + 1); w2 = __ldg(pk + 2);
            w3 = __ldg(pk + 3); w4 = __ldg(pk + 4); w5 = __ldg(pk + 5);
            __half2 nn = __ldg((const __half2*)(g_wn + g));
            float n0f = __half2float(__low2half(nn)), n1f = __half2float(__high2half(nn));
            a0 = n0f * (2.0f / 7.0f); nb0 = -n0f;
            a1 = n1f * (2.0f / 7.0f); nb1 = -n1f;
        }
        // ---- issue A(i+2) cp.async into stage (rd3+2)%3 ----
        if (more2) {
            int wr3 = rd3 + 2; if (wr3 >= 3) wr3 -= 3;
            const uint32_t Aw = As0 + (uint32_t)wr3 * STAGE_BYTES;
            const int ci = c0 + i + 2;
            #pragma unroll
            for (int p = 0; p < 8; p++) {
                int idx = p * NTHREADS + tid;
                int row = idx >> 3, col = idx & 7;
                cpasync16(Aw + (uint32_t)(row * PITCH + col * 16),
                          g_xh + (size_t)(m0 + row) * INF + ci * KCHUNK + col * 8);
            }
            asm volatile("cp.async.commit_group;" ::: "memory");
        }

        // ---- compute chunk i: 4 k16 steps, 32 mma each ----
        #pragma unroll
        for (int ks = 0; ks < 4; ks++) {
            uint32_t af[4][4], bf[4][4];
            #pragma unroll
            for (int mt = 0; mt < 4; mt++) {
                uint32_t addr = As + (uint32_t)((wm * 64 + mt * 16 + a_lrow) * PITCH)
                              + (uint32_t)((ks * 16 + a_lkoff) * 2);
                ldm_x4(af[mt], addr);
            }
            #pragma unroll
            for (int j = 0; j < 4; j++) {
                uint32_t addr = Bs + (uint32_t)((wn_ * 64 + j * 16 + b_lrow) * PITCH)
                              + (uint32_t)((ks * 16 + b_lkoff) * 2);
                ldm_x4(bf[j], addr);
            }
            #pragma unroll
            for (int mt = 0; mt < 4; mt++)
                #pragma unroll
                for (int nt = 0; nt < 8; nt++)
                    mma16816(acc[mt][nt], af[mt], bf[nt >> 1][(nt & 1) * 2], bf[nt >> 1][(nt & 1) * 2 + 1]);
        }

        // ---- stage B(i+1); then ensure A(i+1) landed; sync ----
        if (more) {
            const uint32_t Bw = Bb + (uint32_t)((i + 1) & 1) * STAGE_BYTES;
            sts128(Bw + brow +  0, dec8(w0.x, w0.y, w0.z, a0, nb0));
            sts128(Bw + brow + 16, dec8(w0.w, w1.x, w1.y, a0, nb0));
            sts128(Bw + brow + 32, dec8(w1.z, w1.w, w2.x, a0, nb0));
            sts128(Bw + brow + 48, dec8(w2.y, w2.z, w2.w, a0, nb0));
            sts128(Bw + brow + 64, dec8(w3.x, w3.y, w3.z, a1, nb1));
            sts128(Bw + brow + 80, dec8(w3.w, w4.x, w4.y, a1, nb1));
            sts128(Bw + brow + 96, dec8(w4.z, w4.w, w5.x, a1, nb1));
            sts128(Bw + brow + 112, dec8(w5.y, w5.z, w5.w, a1, nb1));
            if (more2) { asm volatile("cp.async.wait_group 1;" ::: "memory"); }
            else       { asm volatile("cp.async.wait_group 0;" ::: "memory"); }
            __syncthreads();
        }

        rd3++; if (rd3 == 3) rd3 = 0;
    }

    // ---- epilogue: atomic accumulate split-K partials (bias pre-broadcast by prep) ----
    #pragma unroll
    for (int mt = 0; mt < 4; mt++) {
        #pragma unroll
        for (int nt = 0; nt < 8; nt++) {
            int m = m0 + wm * 64 + mt * 16 + (lid >> 2);
            int nl = n0 + wn_ * 64 + nt * 8 + (lid & 3) * 2;
            float* p0 = out + (size_t)m * OUTF + nl;
            float* p1 = out + (size_t)(m + 8) * OUTF + nl;
            atomicAdd(p0,     acc[mt][nt][0]);
            atomicAdd(p0 + 1, acc[mt][nt][1]);
            atomicAdd(p1,     acc[mt][nt][2]);
            atomicAdd(p1 + 1, acc[mt][nt][3]);
        }
    }
}

// ---------------- launch ----------------
extern "C" void kernel_launch(void* const* d_in, const int* in_sizes, int n_in,
                              void* d_out, int out_size) {
    // Bind inputs by element count (robust to metadata ordering).
    const float* x    = 0;
    const int*   wq   = 0;
    const void*  wn   = 0;
    const float* bias = 0;
    for (int i = 0; i < n_in; i++) {
        switch (in_sizes[i]) {
            case N_X:  x    = (const float*)d_in[i]; break;
            case N_WQ: wq   = (const int*)d_in[i];   break;
            case N_WN: wn   = d_in[i];               break;
            case N_B:  bias = (const float*)d_in[i]; break;
            default: break;
        }
    }
    if (!x)    x    = (const float*)d_in[0];
    if (!wq)   wq   = (const int*)d_in[1];
    if (!wn)   wn   = d_in[2];
    if (!bias) bias = (const float*)d_in[3];

    float* out = (float*)d_out;

    cudaFuncSetAttribute(l3b_gemm, cudaFuncAttributeMaxDynamicSharedMemorySize, SMEM_BYTES);

    prep_kernel<<<NB_WN + NB_X + NB_OUT, 512>>>(wn, x, bias, out);

    dim3 grid(MTOT / M_TILE, OUTF / N_TILE, KSPLIT);  // (4, 86, 4)
    l3b_gemm<<<grid, NTHREADS, SMEM_BYTES>>>(wq, out);
}

// round 12
// speedup vs baseline: 1.0435x; 1.0435x over previous
#include <cuda_runtime.h>
#include <cuda_fp16.h>
#include <cuda_bf16.h>
#include <stdint.h>

// Problem constants
#define OUTF   11008
#define INF    4096
#define MTOT   512
#define NUM_GROUPS 1409024               // OUTF*INF/32

#define N_TILE 128
#define M_TILE 128
#define KCHUNK 64
#define KSPLIT 4
#define NCHUNK_JOB (INF / KCHUNK / KSPLIT)   // 16 chunks per job
#define NTHREADS 256                     // 8 warps, warp tile m64 x n32

#define PITCH 144                        // 128B data + 16B pad per row (conflict-free ldmatrix)
#define STAGE_BYTES (128 * PITCH)        // 18432 per tile (A or B)
// A: 3 stages + B: 3 stages
#define SMEM_BYTES (6 * STAGE_BYTES)     // 110592 -> 2 CTAs/SM (221KB of 228KB)

// element counts for input identification (all distinct)
#define N_X   (MTOT * INF)               // 2,097,152 fp32
#define N_WQ  (NUM_GROUPS * 12)          // 16,908,288 int32
#define N_WN  NUM_GROUPS                 // 1,409,024 (dtype auto-detected)
#define N_B   OUTF                       // 11,008 fp32

// prep kernel block partition (512 threads each)
#define NB_WN  (NUM_GROUPS / 512)        // 2752
#define NB_X   (MTOT * INF / 2 / 512)    // 2048
#define NB_OUT (MTOT * OUTF / 4 / 512)   // 2752

__device__ __align__(16) __half g_xh[MTOT * INF];     // fp16 activations (4 MB)
__device__ __align__(16) __half g_wn[NUM_GROUPS];     // normalized norms (2.8 MB)
__device__ __align__(16) __half g_w[(size_t)OUTF * INF];  // dequantized weights (90 MB)

// ---------------- helpers ----------------
__device__ __forceinline__ uint32_t smem_u32(const void* p) {
    uint32_t a;
    asm("{ .reg .u64 t; cvta.to.shared.u64 t, %1; cvt.u32.u64 %0, t; }" : "=r"(a) : "l"(p));
    return a;
}

__device__ __forceinline__ void cpasync16(uint32_t dst, const void* src) {
    asm volatile("cp.async.cg.shared.global [%0], [%1], 16;" :: "r"(dst), "l"(src) : "memory");
}

__device__ __forceinline__ void ldm_x4(uint32_t* r, uint32_t addr) {
    asm volatile("ldmatrix.sync.aligned.m8n8.x4.shared.b16 {%0,%1,%2,%3}, [%4];"
                 : "=r"(r[0]), "=r"(r[1]), "=r"(r[2]), "=r"(r[3]) : "r"(addr));
}

__device__ __forceinline__ void mma16816(float* c, const uint32_t* a, const uint32_t b0, const uint32_t b1) {
    asm volatile(
        "mma.sync.aligned.m16n8k16.row.col.f32.f16.f16.f32 "
        "{%0,%1,%2,%3}, {%4,%5,%6,%7}, {%8,%9}, {%0,%1,%2,%3};"
        : "+f"(c[0]), "+f"(c[1]), "+f"(c[2]), "+f"(c[3])
        : "r"(a[0]), "r"(a[1]), "r"(a[2]), "r"(a[3]), "r"(b0), "r"(b1));
}

// Decode 8 3-bit codes from 3 bytes (each held in an int32), dequantize, pack to 4x half2.
__device__ __forceinline__ uint4 dec8(int b0, int b1, int b2, float a, float nb) {
    float w0 = fmaf((float)(b0 & 7), a, nb);
    float w1 = fmaf((float)((b0 >> 3) & 7), a, nb);
    float w2 = fmaf((float)(((b0 >> 6) & 3) | ((b1 & 1) << 2)), a, nb);
    float w3 = fmaf((float)((b1 >> 1) & 7), a, nb);
    float w4 = fmaf((float)((b1 >> 4) & 7), a, nb);
    float w5 = fmaf((float)(((b1 >> 7) & 1) | ((b2 & 3) << 1)), a, nb);
    float w6 = fmaf((float)((b2 >> 2) & 7), a, nb);
    float w7 = fmaf((float)((b2 >> 5) & 7), a, nb);
    uint4 u;
    asm("cvt.rn.f16x2.f32 %0, %1, %2;" : "=r"(u.x) : "f"(w1), "f"(w0));
    asm("cvt.rn.f16x2.f32 %0, %1, %2;" : "=r"(u.y) : "f"(w3), "f"(w2));
    asm("cvt.rn.f16x2.f32 %0, %1, %2;" : "=r"(u.z) : "f"(w5), "f"(w4));
    asm("cvt.rn.f16x2.f32 %0, %1, %2;" : "=r"(u.w) : "f"(w7), "f"(w6));
    return u;
}

// ---------------- fused prep: wn detect+convert, x convert, out init ----------------
// Norms lie in (0.01, 0.11); each wn-block re-votes locally.
__global__ void __launch_bounds__(512) prep_kernel(
    const void* __restrict__ wn, const float* __restrict__ x,
    const float* __restrict__ bias, float* __restrict__ out)
{
    int b = blockIdx.x;
    if (b < NB_WN) {
        __shared__ int votes[3];
        if (threadIdx.x < 3) votes[threadIdx.x] = 0;
        __syncthreads();
        {
            int j = threadIdx.x & 255;
            float a = ((const float*)wn)[j];
            float h = __half2float(((const __half*)wn)[j]);
            float c = __bfloat162float(((const __nv_bfloat16*)wn)[j]);
            if (a > 0.009f && a < 0.115f) atomicAdd(&votes[0], 1);
            if (h > 0.009f && h < 0.115f) atomicAdd(&votes[1], 1);
            if (c > 0.009f && c < 0.115f) atomicAdd(&votes[2], 1);
        }
        __syncthreads();
        int mode = 1, best = votes[1];
        if (votes[0] > best) { best = votes[0]; mode = 0; }
        if (votes[2] > best) { best = votes[2]; mode = 2; }
        int i = b * 512 + threadIdx.x;
        float v;
        if (mode == 0)      v = ((const float*)wn)[i];
        else if (mode == 1) v = __half2float(((const __half*)wn)[i]);
        else                v = __bfloat162float(((const __nv_bfloat16*)wn)[i]);
        g_wn[i] = __float2half_rn(v);
    } else if (b < NB_WN + NB_X) {
        int i = (b - NB_WN) * 512 + threadIdx.x;
        float2 v = ((const float2*)x)[i];
        ((__half2*)g_xh)[i] = __floats2half2_rn(v.x, v.y);
    } else {
        int i = (b - NB_WN - NB_X) * 512 + threadIdx.x;     // float4 index
        int n4 = (i % (OUTF / 4)) * 4;
        float4 bb = *(const float4*)(bias + n4);
        ((float4*)out)[i] = bb;
    }
}

// ---------------- dequantize W once: 3-bit -> fp16 (one group of 32 per thread) ----------------
__global__ void __launch_bounds__(256) dequant_w_kernel(const int* __restrict__ wq) {
    int g = blockIdx.x * 256 + threadIdx.x;          // group index (row-major contiguous in k)
    const int4* pk = (const int4*)wq + (size_t)g * 3;
    int4 w0 = __ldg(pk), w1 = __ldg(pk + 1), w2 = __ldg(pk + 2);
    float n = __half2float(g_wn[g]);
    float aa = n * (2.0f / 7.0f), nb = -n;
    uint4* dst = (uint4*)(g_w + (size_t)g * 32);     // 32 halves = 4 x uint4
    dst[0] = dec8(w0.x, w0.y, w0.z, aa, nb);
    dst[1] = dec8(w0.w, w1.x, w1.y, aa, nb);
    dst[2] = dec8(w1.z, w1.w, w2.x, aa, nb);
    dst[3] = dec8(w2.y, w2.z, w2.w, aa, nb);
}

// ---------------- pure fp16 GEMM, split-K, 8 warps @ m64n32, 3-stage A+B cp.async ----------------
__global__ void __launch_bounds__(NTHREADS, 2) l3b_gemm(float* __restrict__ out)
{
    extern __shared__ char smem[];
    const uint32_t sb = smem_u32(smem);
    const int tid = threadIdx.x;
    const int wid = tid >> 5, lid = tid & 31;
    const int wm = wid >> 2, wn_ = wid & 3;          // 2x4 warp grid, warp tile m64 x n32
    const int m0 = blockIdx.x * M_TILE;              // m fast-varying: L2 weight reuse
    const int n0 = blockIdx.y * N_TILE;
    const int c0 = blockIdx.z * NCHUNK_JOB;          // split-K chunk base

    const uint32_t As0 = sb;                         // 3 A stages
    const uint32_t Bs0 = sb + 3 * STAGE_BYTES;       // 3 B stages

    // cp.async per-thread mapping: 4 x 16B each for A and B (128 rows x 8 cols of uint4)
    const int ld_row = tid >> 3, ld_col = tid & 7;   // base row 0..31 step 32, col 0..7
    const uint32_t ld_soff = (uint32_t)(ld_row * PITCH + ld_col * 16);
    const __half* ag = g_xh + (size_t)(m0 + ld_row) * INF + ld_col * 8;
    const __half* bg = g_w  + (size_t)(n0 + ld_row) * INF + ld_col * 8;

    // ldmatrix lane addressing
    const uint32_t a_lrow = (uint32_t)(lid & 15);
    const uint32_t a_lkoff = (uint32_t)((lid >> 4) * 8);
    const uint32_t b_lrow = (uint32_t)(((lid >> 4) << 3) + (lid & 7));
    const uint32_t b_lkoff = (uint32_t)(((lid >> 3) & 1) * 8);

    float acc[4][4][4];
    #pragma unroll
    for (int mt = 0; mt < 4; mt++)
        #pragma unroll
        for (int nt = 0; nt < 4; nt++)
            #pragma unroll
            for (int e = 0; e < 4; e++) acc[mt][nt][e] = 0.0f;

    // ---- prologue: stage chunks c0 -> stage0, c0+1 -> stage1 (A and B per group) ----
    #pragma unroll
    for (int s = 0; s < 2; s++) {
        const uint32_t As = As0 + (uint32_t)s * STAGE_BYTES;
        const uint32_t Bs = Bs0 + (uint32_t)s * STAGE_BYTES;
        const int koff = (c0 + s) * KCHUNK;
        #pragma unroll
        for (int p = 0; p < 4; p++) {
            cpasync16(As + ld_soff + (uint32_t)(p * 32 * PITCH), ag + (size_t)(p * 32) * INF + koff);
            cpasync16(Bs + ld_soff + (uint32_t)(p * 32 * PITCH), bg + (size_t)(p * 32) * INF + koff);
        }
        asm volatile("cp.async.commit_group;" ::: "memory");
    }
    asm volatile("cp.async.wait_group 1;" ::: "memory");   // chunk c0 landed
    __syncthreads();

    int rd3 = 0;                                     // read stage (i % 3)

    #pragma unroll 1
    for (int i = 0; i < NCHUNK_JOB; i++) {
        const uint32_t As = As0 + (uint32_t)rd3 * STAGE_BYTES;
        const uint32_t Bs = Bs0 + (uint32_t)rd3 * STAGE_BYTES;

        const bool more = (i + 1 < NCHUNK_JOB);
        const bool more2 = (i + 2 < NCHUNK_JOB);

        // ---- issue chunk i+2 cp.async into stage (rd3+2)%3 ----
        if (more2) {
            int wr3 = rd3 + 2; if (wr3 >= 3) wr3 -= 3;
            const uint32_t Aw = As0 + (uint32_t)wr3 * STAGE_BYTES;
            const uint32_t Bw = Bs0 + (uint32_t)wr3 * STAGE_BYTES;
            const int koff = (c0 + i + 2) * KCHUNK;
            #pragma unroll
            for (int p = 0; p < 4; p++) {
                cpasync16(Aw + ld_soff + (uint32_t)(p * 32 * PITCH), ag + (size_t)(p * 32) * INF + koff);
                cpasync16(Bw + ld_soff + (uint32_t)(p * 32 * PITCH), bg + (size_t)(p * 32) * INF + koff);
            }
            asm volatile("cp.async.commit_group;" ::: "memory");
        }

        // ---- compute chunk i: 4 k16 steps, 16 mma each ----
        #pragma unroll
        for (int ks = 0; ks < 4; ks++) {
            uint32_t af[4][4], bf[2][4];
            #pragma unroll
            for (int mt = 0; mt < 4; mt++) {
                uint32_t addr = As + (uint32_t)((wm * 64 + mt * 16 + a_lrow) * PITCH)
                              + (uint32_t)((ks * 16 + a_lkoff) * 2);
                ldm_x4(af[mt], addr);
            }
            #pragma unroll
            for (int nt2 = 0; nt2 < 2; nt2++) {
                uint32_t addr = Bs + (uint32_t)((wn_ * 32 + nt2 * 16 + b_lrow) * PITCH)
                              + (uint32_t)((ks * 16 + b_lkoff) * 2);
                ldm_x4(bf[nt2], addr);
            }
            #pragma unroll
            for (int mt = 0; mt < 4; mt++)
                #pragma unroll
                for (int nt = 0; nt < 4; nt++)
                    mma16816(acc[mt][nt], af[mt], bf[nt >> 1][(nt & 1) * 2], bf[nt >> 1][(nt & 1) * 2 + 1]);
        }

        // ---- ensure chunk i+1 landed; sync stage rotation ----
        if (more) {
            if (more2) { asm volatile("cp.async.wait_group 1;" ::: "memory"); }
            else       { asm volatile("cp.async.wait_group 0;" ::: "memory"); }
            __syncthreads();
        }

        rd3++; if (rd3 == 3) rd3 = 0;
    }

    // ---- epilogue: atomic accumulate split-K partials (bias pre-broadcast by prep) ----
    #pragma unroll
    for (int mt = 0; mt < 4; mt++) {
        #pragma unroll
        for (int nt = 0; nt < 4; nt++) {
            int m = m0 + wm * 64 + mt * 16 + (lid >> 2);
            int nl = n0 + wn_ * 32 + nt * 8 + (lid & 3) * 2;
            float* p0 = out + (size_t)m * OUTF + nl;
            float* p1 = out + (size_t)(m + 8) * OUTF + nl;
            atomicAdd(p0,     acc[mt][nt][0]);
            atomicAdd(p0 + 1, acc[mt][nt][1]);
            atomicAdd(p1,     acc[mt][nt][2]);
            atomicAdd(p1 + 1, acc[mt][nt][3]);
        }
    }
}

// ---------------- launch ----------------
extern "C" void kernel_launch(void* const* d_in, const int* in_sizes, int n_in,
                              void* d_out, int out_size) {
    // Bind inputs by element count (robust to metadata ordering).
    const float* x    = 0;
    const int*   wq   = 0;
    const void*  wn   = 0;
    const float* bias = 0;
    for (int i = 0; i < n_in; i++) {
        switch (in_sizes[i]) {
            case N_X:  x    = (const float*)d_in[i]; break;
            case N_WQ: wq   = (const int*)d_in[i];   break;
            case N_WN: wn   = d_in[i];               break;
            case N_B:  bias = (const float*)d_in[i]; break;
            default: break;
        }
    }
    if (!x)    x    = (const float*)d_in[0];
    if (!wq)   wq   = (const int*)d_in[1];
    if (!wn)   wn   = d_in[2];
    if (!bias) bias = (const float*)d_in[3];

    float* out = (float*)d_out;

    cudaFuncSetAttribute(l3b_gemm, cudaFuncAttributeMaxDynamicSharedMemorySize, SMEM_BYTES);

    prep_kernel<<<NB_WN + NB_X + NB_OUT, 512>>>(wn, x, bias, out);
    dequant_w_kernel<<<NUM_GROUPS / 256, 256>>>(wq);

    dim3 grid(MTOT / M_TILE, OUTF / N_TILE, KSPLIT);  // (4, 86, 4)
    l3b_gemm<<<grid, NTHREADS, SMEM_BYTES>>>(out);
}

// round 13
// speedup vs baseline: 1.0651x; 1.0207x over previous
#include <cuda_runtime.h>
#include <cuda_fp16.h>
#include <cuda_bf16.h>
#include <stdint.h>

// Problem constants
#define OUTF   11008
#define INF    4096
#define MTOT   512
#define NUM_GROUPS 1409024               // OUTF*INF/32

#define N_TILE 128
#define M_TILE 128
#define KCHUNK 64
#define KSPLIT 4
#define NCHUNK_JOB (INF / KCHUNK / KSPLIT)   // 16 chunks per job
#define NTHREADS 256                     // 8 warps, warp tile m64 x n32

#define PITCH 144                        // 128B data + 16B pad per row (conflict-free ldmatrix)
#define STAGE_BYTES (128 * PITCH)        // 18432 per tile (A or B)
// A: 3 stages + B: 3 stages
#define SMEM_BYTES (6 * STAGE_BYTES)     // 110592 -> 2 CTAs/SM (221KB of 228KB)

// element counts for input identification (all distinct)
#define N_X   (MTOT * INF)               // 2,097,152 fp32
#define N_WQ  (NUM_GROUPS * 12)          // 16,908,288 int32
#define N_WN  NUM_GROUPS                 // 1,409,024 (dtype auto-detected)
#define N_B   OUTF                       // 11,008 fp32

// fused prep partition (512 threads per block)
#define NB_DQ  (NUM_GROUPS / 512)        // 2752  (dequant: 1 group/thread)
#define NB_X   (MTOT * INF / 2 / 512)    // 2048  (x convert: 1 half2/thread)
#define NB_OUT (MTOT * OUTF / 4 / 512)   // 2752  (out init: 1 float4/thread)

__device__ __align__(16) __half g_xh[MTOT * INF];     // fp16 activations (4 MB)
__device__ __align__(16) __half g_w[(size_t)OUTF * INF];  // dequantized weights (90 MB)

// ---------------- helpers ----------------
__device__ __forceinline__ uint32_t smem_u32(const void* p) {
    uint32_t a;
    asm("{ .reg .u64 t; cvta.to.shared.u64 t, %1; cvt.u32.u64 %0, t; }" : "=r"(a) : "l"(p));
    return a;
}

__device__ __forceinline__ void cpasync16(uint32_t dst, const void* src) {
    asm volatile("cp.async.cg.shared.global [%0], [%1], 16;" :: "r"(dst), "l"(src) : "memory");
}

__device__ __forceinline__ void ldm_x4(uint32_t* r, uint32_t addr) {
    asm volatile("ldmatrix.sync.aligned.m8n8.x4.shared.b16 {%0,%1,%2,%3}, [%4];"
                 : "=r"(r[0]), "=r"(r[1]), "=r"(r[2]), "=r"(r[3]) : "r"(addr));
}

__device__ __forceinline__ void mma16816(float* c, const uint32_t* a, const uint32_t b0, const uint32_t b1) {
    asm volatile(
        "mma.sync.aligned.m16n8k16.row.col.f32.f16.f16.f32 "
        "{%0,%1,%2,%3}, {%4,%5,%6,%7}, {%8,%9}, {%0,%1,%2,%3};"
        : "+f"(c[0]), "+f"(c[1]), "+f"(c[2]), "+f"(c[3])
        : "r"(a[0]), "r"(a[1]), "r"(a[2]), "r"(a[3]), "r"(b0), "r"(b1));
}

// Decode 8 3-bit codes from 3 bytes (each held in an int32), dequantize, pack to 4x half2.
__device__ __forceinline__ uint4 dec8(int b0, int b1, int b2, float a, float nb) {
    float w0 = fmaf((float)(b0 & 7), a, nb);
    float w1 = fmaf((float)((b0 >> 3) & 7), a, nb);
    float w2 = fmaf((float)(((b0 >> 6) & 3) | ((b1 & 1) << 2)), a, nb);
    float w3 = fmaf((float)((b1 >> 1) & 7), a, nb);
    float w4 = fmaf((float)((b1 >> 4) & 7), a, nb);
    float w5 = fmaf((float)(((b1 >> 7) & 1) | ((b2 & 3) << 1)), a, nb);
    float w6 = fmaf((float)((b2 >> 2) & 7), a, nb);
    float w7 = fmaf((float)((b2 >> 5) & 7), a, nb);
    uint4 u;
    asm("cvt.rn.f16x2.f32 %0, %1, %2;" : "=r"(u.x) : "f"(w1), "f"(w0));
    asm("cvt.rn.f16x2.f32 %0, %1, %2;" : "=r"(u.y) : "f"(w3), "f"(w2));
    asm("cvt.rn.f16x2.f32 %0, %1, %2;" : "=r"(u.z) : "f"(w5), "f"(w4));
    asm("cvt.rn.f16x2.f32 %0, %1, %2;" : "=r"(u.w) : "f"(w7), "f"(w6));
    return u;
}

// ---------------- fused prep: W dequant (with local wn-dtype vote), x convert, out init ----
// Norms lie in (0.01, 0.11); dequant blocks re-vote dtype locally over wn[0..255].
__global__ void __launch_bounds__(512) prep_kernel(
    const void* __restrict__ wn, const int* __restrict__ wq,
    const float* __restrict__ x, const float* __restrict__ bias,
    float* __restrict__ out)
{
    int b = blockIdx.x;
    if (b < NB_DQ) {
        __shared__ int votes[3];
        if (threadIdx.x < 3) votes[threadIdx.x] = 0;
        __syncthreads();
        {
            int j = threadIdx.x & 255;
            float a = ((const float*)wn)[j];
            float h = __half2float(((const __half*)wn)[j]);
            float c = __bfloat162float(((const __nv_bfloat16*)wn)[j]);
            if (a > 0.009f && a < 0.115f) atomicAdd(&votes[0], 1);
            if (h > 0.009f && h < 0.115f) atomicAdd(&votes[1], 1);
            if (c > 0.009f && c < 0.115f) atomicAdd(&votes[2], 1);
        }
        __syncthreads();
        int mode = 1, best = votes[1];
        if (votes[0] > best) { best = votes[0]; mode = 0; }
        if (votes[2] > best) { best = votes[2]; mode = 2; }

        int g = b * 512 + threadIdx.x;               // group index (contiguous in k)
        float n;
        if (mode == 0)      n = ((const float*)wn)[g];
        else if (mode == 1) n = __half2float(((const __half*)wn)[g]);
        else                n = __bfloat162float(((const __nv_bfloat16*)wn)[g]);
        const int4* pk = (const int4*)wq + (size_t)g * 3;
        int4 w0 = __ldg(pk), w1 = __ldg(pk + 1), w2 = __ldg(pk + 2);
        float aa = n * (2.0f / 7.0f), nb = -n;
        uint4* dst = (uint4*)(g_w + (size_t)g * 32);  // 32 halves = 4 x uint4
        dst[0] = dec8(w0.x, w0.y, w0.z, aa, nb);
        dst[1] = dec8(w0.w, w1.x, w1.y, aa, nb);
        dst[2] = dec8(w1.z, w1.w, w2.x, aa, nb);
        dst[3] = dec8(w2.y, w2.z, w2.w, aa, nb);
    } else if (b < NB_DQ + NB_X) {
        int i = (b - NB_DQ) * 512 + threadIdx.x;
        float2 v = ((const float2*)x)[i];
        ((__half2*)g_xh)[i] = __floats2half2_rn(v.x, v.y);
    } else {
        int i = (b - NB_DQ - NB_X) * 512 + threadIdx.x;     // float4 index
        int n4 = (i % (OUTF / 4)) * 4;
        float4 bb = *(const float4*)(bias + n4);
        ((float4*)out)[i] = bb;
    }
}

// ---------------- pure fp16 GEMM, split-K, 8 warps @ m64n32, 3-stage A+B cp.async,
// ---------------- A-fragment double buffering inside the k-loop ----------------
__global__ void __launch_bounds__(NTHREADS, 2) l3b_gemm(float* __restrict__ out)
{
    extern __shared__ char smem[];
    const uint32_t sb = smem_u32(smem);
    const int tid = threadIdx.x;
    const int wid = tid >> 5, lid = tid & 31;
    const int wm = wid >> 2, wn_ = wid & 3;          // 2x4 warp grid, warp tile m64 x n32
    const int m0 = blockIdx.x * M_TILE;              // m fast-varying: L2 weight reuse
    const int n0 = blockIdx.y * N_TILE;
    const int c0 = blockIdx.z * NCHUNK_JOB;          // split-K chunk base

    const uint32_t As0 = sb;                         // 3 A stages
    const uint32_t Bs0 = sb + 3 * STAGE_BYTES;       // 3 B stages

    // cp.async per-thread mapping: 4 x 16B each for A and B (128 rows x 8 cols of uint4)
    const int ld_row = tid >> 3, ld_col = tid & 7;   // base row 0..31 step 32, col 0..7
    const uint32_t ld_soff = (uint32_t)(ld_row * PITCH + ld_col * 16);
    const __half* ag = g_xh + (size_t)(m0 + ld_row) * INF + ld_col * 8;
    const __half* bg = g_w  + (size_t)(n0 + ld_row) * INF + ld_col * 8;

    // ldmatrix lane base offsets (within a stage)
    const uint32_t a_loff = (uint32_t)((wm * 64 + (lid & 15)) * PITCH + ((lid >> 4) * 8) * 2);
    const uint32_t b_loff = (uint32_t)((wn_ * 32 + ((lid >> 4) << 3) + (lid & 7)) * PITCH
                                       + (((lid >> 3) & 1) * 8) * 2);

    float acc[4][4][4];
    #pragma unroll
    for (int mt = 0; mt < 4; mt++)
        #pragma unroll
        for (int nt = 0; nt < 4; nt++)
            #pragma unroll
            for (int e = 0; e < 4; e++) acc[mt][nt][e] = 0.0f;

    // ---- prologue: stage chunks c0 -> stage0, c0+1 -> stage1 (A and B per group) ----
    #pragma unroll
    for (int s = 0; s < 2; s++) {
        const uint32_t As = As0 + (uint32_t)s * STAGE_BYTES;
        const uint32_t Bs = Bs0 + (uint32_t)s * STAGE_BYTES;
        const int koff = (c0 + s) * KCHUNK;
        #pragma unroll
        for (int p = 0; p < 4; p++) {
            cpasync16(As + ld_soff + (uint32_t)(p * 32 * PITCH), ag + (size_t)(p * 32) * INF + koff);
            cpasync16(Bs + ld_soff + (uint32_t)(p * 32 * PITCH), bg + (size_t)(p * 32) * INF + koff);
        }
        asm volatile("cp.async.commit_group;" ::: "memory");
    }
    asm volatile("cp.async.wait_group 1;" ::: "memory");   // chunk c0 landed
    __syncthreads();

    int rd3 = 0;                                     // read stage (i % 3)

    #pragma unroll 1
    for (int i = 0; i < NCHUNK_JOB; i++) {
        const uint32_t As = As0 + (uint32_t)rd3 * STAGE_BYTES;
        const uint32_t Bs = Bs0 + (uint32_t)rd3 * STAGE_BYTES;

        const bool more = (i + 1 < NCHUNK_JOB);
        const bool more2 = (i + 2 < NCHUNK_JOB);

        // ---- issue chunk i+2 cp.async into stage (rd3+2)%3 ----
        if (more2) {
            int wr3 = rd3 + 2; if (wr3 >= 3) wr3 -= 3;
            const uint32_t Aw = As0 + (uint32_t)wr3 * STAGE_BYTES;
            const uint32_t Bw = Bs0 + (uint32_t)wr3 * STAGE_BYTES;
            const int koff = (c0 + i + 2) * KCHUNK;
            #pragma unroll
            for (int p = 0; p < 4; p++) {
                cpasync16(Aw + ld_soff + (uint32_t)(p * 32 * PITCH), ag + (size_t)(p * 32) * INF + koff);
                cpasync16(Bw + ld_soff + (uint32_t)(p * 32 * PITCH), bg + (size_t)(p * 32) * INF + koff);
            }
            asm volatile("cp.async.commit_group;" ::: "memory");
        }

        // ---- compute chunk i: 4 k16 steps, A-fragments double-buffered ----
        {
            uint32_t af[2][4][4], bf[2][4];
            // preload k-step 0
            #pragma unroll
            for (int mt = 0; mt < 4; mt++)
                ldm_x4(af[0][mt], As + a_loff + (uint32_t)(mt * 16 * PITCH));
            #pragma unroll
            for (int nt2 = 0; nt2 < 2; nt2++)
                ldm_x4(bf[nt2], Bs + b_loff + (uint32_t)(nt2 * 16 * PITCH));

            #pragma unroll
            for (int ks = 0; ks < 4; ks++) {
                const int cur = ks & 1, nxt = cur ^ 1;
                // prefetch A fragments of k-step ks+1 (overlaps with MMAs below)
                if (ks < 3) {
                    #pragma unroll
                    for (int mt = 0; mt < 4; mt++)
                        ldm_x4(af[nxt][mt], As + a_loff + (uint32_t)(mt * 16 * PITCH + (ks + 1) * 32));
                }
                // 16 MMAs of k-step ks
                #pragma unroll
                for (int mt = 0; mt < 4; mt++)
                    #pragma unroll
                    for (int nt = 0; nt < 4; nt++)
                        mma16816(acc[mt][nt], af[cur][mt],
                                 bf[nt >> 1][(nt & 1) * 2], bf[nt >> 1][(nt & 1) * 2 + 1]);
                // load B fragments of k-step ks+1 (after last use of bf)
                if (ks < 3) {
                    #pragma unroll
                    for (int nt2 = 0; nt2 < 2; nt2++)
                        ldm_x4(bf[nt2], Bs + b_loff + (uint32_t)(nt2 * 16 * PITCH + (ks + 1) * 32));
                }
            }
        }

        // ---- ensure chunk i+1 landed; sync stage rotation ----
        if (more) {
            if (more2) { asm volatile("cp.async.wait_group 1;" ::: "memory"); }
            else       { asm volatile("cp.async.wait_group 0;" ::: "memory"); }
            __syncthreads();
        }

        rd3++; if (rd3 == 3) rd3 = 0;
    }

    // ---- epilogue: atomic accumulate split-K partials (bias pre-broadcast by prep) ----
    #pragma unroll
    for (int mt = 0; mt < 4; mt++) {
        #pragma unroll
        for (int nt = 0; nt < 4; nt++) {
            int m = m0 + wm * 64 + mt * 16 + (lid >> 2);
            int nl = n0 + wn_ * 32 + nt * 8 + (lid & 3) * 2;
            float* p0 = out + (size_t)m * OUTF + nl;
            float* p1 = out + (size_t)(m + 8) * OUTF + nl;
            atomicAdd(p0,     acc[mt][nt][0]);
            atomicAdd(p0 + 1, acc[mt][nt][1]);
            atomicAdd(p1,     acc[mt][nt][2]);
            atomicAdd(p1 + 1, acc[mt][nt][3]);
        }
    }
}

// ---------------- launch ----------------
extern "C" void kernel_launch(void* const* d_in, const int* in_sizes, int n_in,
                              void* d_out, int out_size) {
    // Bind inputs by element count (robust to metadata ordering).
    const float* x    = 0;
    const int*   wq   = 0;
    const void*  wn   = 0;
    const float* bias = 0;
    for (int i = 0; i < n_in; i++) {
        switch (in_sizes[i]) {
            case N_X:  x    = (const float*)d_in[i]; break;
            case N_WQ: wq   = (const int*)d_in[i];   break;
            case N_WN: wn   = d_in[i];               break;
            case N_B:  bias = (const float*)d_in[i]; break;
            default: break;
        }
    }
    if (!x)    x    = (const float*)d_in[0];
    if (!wq)   wq   = (const int*)d_in[1];
    if (!wn)   wn   = d_in[2];
    if (!bias) bias = (const float*)d_in[3];

    float* out = (float*)d_out;

    cudaFuncSetAttribute(l3b_gemm, cudaFuncAttributeMaxDynamicSharedMemorySize, SMEM_BYTES);

    prep_kernel<<<NB_DQ + NB_X + NB_OUT, 512>>>(wn, wq, x, bias, out);

    dim3 grid(MTOT / M_TILE, OUTF / N_TILE, KSPLIT);  // (4, 86, 4)
    l3b_gemm<<<grid, NTHREADS, SMEM_BYTES>>>(out);
}